// round 16
// baseline (speedup 1.0000x reference)
#include <cuda_runtime.h>
#include <cuda_fp16.h>
#include <math.h>
#include <stdint.h>

// Problem constants
#define BB 4
#define TT 2048
#define EE 1024
#define HH 16
#define HD 64
#define MM (BB*TT)          // 8192 rows
#define E2 (EE/2)           // 512 pairs
#define GK 1024

// Q is pre-scaled by 0.125*log2(e) so flash softmax runs in base-2 domain.
#define QSCALE 0.18033688011112042f

// ---------------- scratch (device globals; no allocation allowed) ----------
__device__ float g_theta[E2];

__device__ __align__(256) __half g_rxh [MM*EE];   // RoPE(x), fp16
__device__ __align__(256) __half g_xh  [MM*EE];   // x, fp16
__device__ __align__(256) __half g_qh  [MM*EE];   // Q fp16 (pre-scaled)
__device__ __align__(256) __half g_kh  [MM*EE];   // K fp16
__device__ __align__(256) __half g_vh  [MM*EE];   // V fp16
__device__ __align__(256) __half g_ath [MM*EE];   // attention out fp16
__device__ __align__(256) __half g_wh  [4][EE*EE];  // Wq,Wk,Wv,Wo fp16

// ================= helpers (compute_80-level PTX only!) =====================
__device__ __forceinline__ uint32_t smem_u32(const void* p) {
    uint32_t a;
    asm("{ .reg .u64 t; cvta.to.shared.u64 t, %1; cvt.u32.u64 %0, t; }"
        : "=r"(a) : "l"(p));
    return a;
}
__device__ __forceinline__ void cp16(uint32_t saddr, const void* g) {
    asm volatile("cp.async.cg.shared.global [%0], [%1], 16;"
                 :: "r"(saddr), "l"(g) : "memory");
}
#define CP_COMMIT() asm volatile("cp.async.commit_group;" ::: "memory")
#define CP_WAIT(n)  asm volatile("cp.async.wait_group %0;" :: "n"(n) : "memory")

__device__ __forceinline__ void ldsm_x4(uint32_t* r, uint32_t addr) {
    asm volatile("ldmatrix.sync.aligned.m8n8.x4.shared.b16 {%0,%1,%2,%3}, [%4];"
                 : "=r"(r[0]), "=r"(r[1]), "=r"(r[2]), "=r"(r[3]) : "r"(addr));
}
__device__ __forceinline__ void ldsm_x4_t(uint32_t* r, uint32_t addr) {
    asm volatile("ldmatrix.sync.aligned.m8n8.x4.trans.shared.b16 {%0,%1,%2,%3}, [%4];"
                 : "=r"(r[0]), "=r"(r[1]), "=r"(r[2]), "=r"(r[3]) : "r"(addr));
}
__device__ __forceinline__ void mma_fp16(float* c, const uint32_t* a,
                                         const uint32_t* b) {
    asm volatile(
        "mma.sync.aligned.m16n8k16.row.col.f32.f16.f16.f32 "
        "{%0,%1,%2,%3}, {%4,%5,%6,%7}, {%8,%9}, {%0,%1,%2,%3};"
        : "+f"(c[0]), "+f"(c[1]), "+f"(c[2]), "+f"(c[3])
        : "r"(a[0]), "r"(a[1]), "r"(a[2]), "r"(a[3]), "r"(b[0]), "r"(b[1]));
}
// packed half2 2^x (one MUFU for two elements)
__device__ __forceinline__ uint32_t h2ex2(uint32_t x) {
    uint32_t r;
    asm("ex2.approx.f16x2 %0, %1;" : "=r"(r) : "r"(x));
    return r;
}

// ---------------- theta table ------------------------------------------------
__global__ void theta_kernel() {
    int p = blockIdx.x * blockDim.x + threadIdx.x;
    if (p >= E2) return;
    g_theta[p] = (float)exp((-(double)(2*p) / (double)EE) * log(10000.0));
}

// ---------------- fused RoPE (fp16 out) + x fp16 ------------------------------
#define P2HI 6.2831854820251465f
#define P2LO -1.7484555e-7f
#define INV2PI 0.15915494309189535f

__global__ void rope_fused_kernel(const float* __restrict__ x) {
    int idx = blockIdx.x * blockDim.x + threadIdx.x;   // over MM*E2 pairs
    if (idx >= MM*E2) return;
    int bt = idx / E2;
    int p  = idx % E2;
    int t  = bt % TT;
    float2 v = ((const float2*)x)[idx];
    float ang = (float)t * g_theta[p];      // fp32 rounding as in reference
    float n = rintf(ang * INV2PI);
    float r = fmaf(-n, P2HI, ang);
    r = fmaf(-n, P2LO, r);
    float s, c;
    __sincosf(r, &s, &c);                   // |r|<=pi: approx err ~1e-6 << fp16
    float rx = v.x * c - v.y * s;
    float ry = v.y * c + v.x * s;
    ((__half2*)g_rxh)[idx] = __floats2half2_rn(rx, ry);
    ((__half2*)g_xh)[idx]  = __floats2half2_rn(v.x, v.y);
}

// ---------------- all-W fp16 convert (one launch) -----------------------------
__global__ void split_all_kernel(const float* __restrict__ Wq,
                                 const float* __restrict__ Wk,
                                 const float* __restrict__ Wv,
                                 const float* __restrict__ Wo) {
    int i = blockIdx.x * blockDim.x + threadIdx.x;
    if (i >= EE*EE) return;
    int w = blockIdx.y;
    const float* src = (w == 0) ? Wq : (w == 1) ? Wk : (w == 2) ? Wv : Wo;
    g_wh[w][i] = __float2half_rn(src[i]);
}

// ---------------- persistent single-term fp16 NT GEMM, 3-stage, 2 CTAs/SM ----
// Register-level software pipeline: fragments for k16+1 are loaded while
// k16's MMAs issue (a[2][..], wt[2][..] double buffers).
#define KSTEPS (GK/64)          // 16
#define TILE_B 16384            // 128 rows x 128 bytes
#define STG16_B (2*TILE_B)      // A|W = 32 KB
#define GEMM16_SMEM (3*STG16_B) // 96 KB -> 2 CTAs/SM
#define GPERS_GRID 304          // 152 SMs x 2 CTAs

template<int OUT>
__global__ __launch_bounds__(256, 2)
void hmma_gemm16_kernel(const __half* __restrict__ A0,
                        const __half* __restrict__ A2,
                        const __half* __restrict__ W0,
                        __half* __restrict__ C16_0,
                        __half* __restrict__ C16_1,
                        __half* __restrict__ C16_2,
                        float* __restrict__ C32,
                        const float* __restrict__ bias) {
    extern __shared__ char sm[];
    const int tid  = threadIdx.x;
    const int wid  = tid >> 5;
    const int lane = tid & 31;
    const uint32_t sbase = smem_u32(sm);
    const int wm = wid >> 2;
    const int wn = wid & 3;
    const int G  = (int)gridDim.x;
    const int bx = (int)blockIdx.x;
    const int T  = (OUT == 0) ? 1536 : 512;
    const int nt = (T - bx + G - 1) / G;
    const int NC = nt << 4;

    auto tile_of = [&](int c, int& z, int& r0, int& c0) {
        int t = bx + (c >> 4) * G;
        if (OUT == 0) { z = t / 512; int rem = t & 511; r0 = (rem >> 3) << 7; c0 = (rem & 7) << 7; }
        else          { z = 3;       r0 = (t >> 3) << 7; c0 = (t & 7) << 7; }
    };

    auto load_chunk = [&](int s, int c) {
        if (c >= NC) return;
        int z, r0, c0; tile_of(c, z, r0, c0);
        const int k0 = (c & 15) * 64;
        const __half* A = (OUT == 0 && z == 2) ? A2 : A0;
        const __half* srcs[2] = { A, W0 + (size_t)z*EE*EE };
        const uint32_t st = sbase + s * STG16_B;
        #pragma unroll
        for (int t = 0; t < 2; t++) {
            const int rb = (t == 0) ? r0 : c0;
            #pragma unroll
            for (int it = 0; it < 4; it++) {
                int u = tid + 256 * it;
                int r = u >> 3, cc = u & 7;
                const __half* g = srcs[t] + (size_t)(rb + r) * GK + k0 + cc * 8;
                uint32_t sa = st + t * TILE_B + r * 128 + ((cc ^ (r & 7)) * 16);
                cp16(sa, g);
            }
        }
    };

    load_chunk(0, 0); CP_COMMIT();
    load_chunk(1, 1); CP_COMMIT();

    float acc[4][4][4] = {};
    const int lr = lane & 15, lc = lane >> 4;

    uint32_t sw[4];
    #pragma unroll
    for (int k16 = 0; k16 < 4; k16++)
        sw[k16] = (uint32_t)(((k16*2 + lc) ^ (lr & 7)) * 16);
    const uint32_t baseA = (uint32_t)((wm*64 + lr) * 128);
    const uint32_t baseW = (uint32_t)((wn*32 + lr) * 128);

    for (int c = 0; c < NC; c++) {
        CP_WAIT(1);
        __syncthreads();
        // stage (c+2)%3 was consumed in chunk c-1 (ordered by this barrier)
        load_chunk((c + 2) % 3, c + 2);
        CP_COMMIT();

        const uint32_t st = sbase + (c % 3) * STG16_B;
        const uint32_t aB = st + baseA;
        const uint32_t whB = st + TILE_B + baseW;

        // ---- register software pipeline over k16 ----
        uint32_t a[2][4][4], wt[2][2][4];
        auto ldfrag = [&](int k16, int buf) {
            const uint32_t s16 = sw[k16];
            #pragma unroll
            for (int i = 0; i < 4; i++)
                ldsm_x4(a[buf][i], aB + i*2048 + s16);
            #pragma unroll
            for (int jj = 0; jj < 2; jj++)
                ldsm_x4(wt[buf][jj], whB + jj*2048 + s16);
        };
        ldfrag(0, 0);
        #pragma unroll
        for (int k16 = 0; k16 < 4; k16++) {
            const int cur = k16 & 1;
            if (k16 < 3) ldfrag(k16 + 1, cur ^ 1);
            #pragma unroll
            for (int jj = 0; jj < 2; jj++) {
                uint32_t b0[2] = { wt[cur][jj][0], wt[cur][jj][2] };
                uint32_t b1[2] = { wt[cur][jj][1], wt[cur][jj][3] };
                #pragma unroll
                for (int i = 0; i < 4; i++) {
                    mma_fp16(acc[i][jj*2],   a[cur][i], b0);
                    mma_fp16(acc[i][jj*2+1], a[cur][i], b1);
                }
            }
        }

        if ((c & 15) == 15) {
            int z, r0, c0; tile_of(c, z, r0, c0);
            const int gq = lane >> 2, tig = lane & 3;
            __half* C16 = (OUT == 0)
                ? ((z == 0) ? C16_0 : (z == 1) ? C16_1 : C16_2) : nullptr;
            const float osc = (OUT == 0 && z == 0) ? QSCALE : 1.f;
            #pragma unroll
            for (int j = 0; j < 4; j++) {
                const int n = c0 + wn*32 + j*8 + tig*2;
                float b0 = 0.f, b1 = 0.f;
                if (OUT == 1) { b0 = bias[n]; b1 = bias[n+1]; }
                #pragma unroll
                for (int i = 0; i < 4; i++) {
                    const int m0 = r0 + wm*64 + i*16 + gq;
                    if (OUT == 0) {
                        *(__half2*)(C16 + (size_t)m0*GK + n) =
                            __floats2half2_rn(acc[i][j][0]*osc, acc[i][j][1]*osc);
                        *(__half2*)(C16 + (size_t)(m0+8)*GK + n) =
                            __floats2half2_rn(acc[i][j][2]*osc, acc[i][j][3]*osc);
                    } else {
                        *(float2*)(C32 + (size_t)m0 * GK + n) =
                            make_float2(acc[i][j][0] + b0, acc[i][j][1] + b1);
                        *(float2*)(C32 + (size_t)(m0 + 8) * GK + n) =
                            make_float2(acc[i][j][2] + b0, acc[i][j][3] + b1);
                    }
                }
            }
            #pragma unroll
            for (int i = 0; i < 4; i++)
                #pragma unroll
                for (int j = 0; j < 4; j++) {
                    acc[i][j][0] = 0.f; acc[i][j][1] = 0.f;
                    acc[i][j][2] = 0.f; acc[i][j][3] = 0.f;
                }
        }
    }
}

// ---------------- HMMA flash attention (causal, fp16, base-2 softmax) --------
#define FL_QB   16384
#define FL_TB   8192
#define FL_STG  (2*FL_TB)
#define FL_NSTG 3
#define FL_SMEM (FL_QB + FL_NSTG*FL_STG)   // 64 KB

__global__ __launch_bounds__(256, 2)
void flash_hmma_kernel(const __half* __restrict__ qh,
                       const __half* __restrict__ kh,
                       const __half* __restrict__ vh,
                       __half* __restrict__ oh) {
    extern __shared__ char sm[];
    const int tid  = threadIdx.x;
    const int wid  = tid >> 5;
    const int lane = tid & 31;
    const int qt = (int)(gridDim.x - 1 - blockIdx.x);   // heavy tiles first
    const int bh = blockIdx.y;
    const int b = bh >> 4, h = bh & 15;
    const int qrow0 = qt * 128;
    const size_t grow0 = (size_t)b * TT + qrow0;
    const int colb = h * HD;

    const uint32_t sb  = smem_u32(sm);
    const uint32_t qB  = sb;
    const uint32_t stB = sb + FL_QB;

    #pragma unroll
    for (int it = 0; it < 4; it++) {
        int u = tid + 256 * it;
        int r = u >> 3, c = u & 7;
        cp16(qB + r*128 + ((c ^ (r & 7)) * 16),
             qh + (grow0 + r) * EE + colb + c * 8);
    }
    const __half* ksrc[2] = { kh, vh };
    auto load_stage = [&](int s, int kt) {
        const size_t krow = (size_t)b * TT + kt * 64;
        const uint32_t st = stB + s * FL_STG;
        #pragma unroll
        for (int t = 0; t < 2; t++) {
            #pragma unroll
            for (int it = 0; it < 2; it++) {
                int u = tid + 256 * it;
                int r = u >> 3, c = u & 7;
                cp16(st + t*FL_TB + r*128 + ((c ^ (r & 7)) * 16),
                     ksrc[t] + (krow + r) * EE + colb + c * 8);
            }
        }
    };
    const int nkv = 2*qt + 2;
    load_stage(0, 0); CP_COMMIT();
    if (1 < nkv) load_stage(1, 1);
    CP_COMMIT();

    CP_WAIT(1);
    __syncthreads();

    const int lr = lane & 15, lc = lane >> 4;
    uint32_t sw[4];
    #pragma unroll
    for (int k16 = 0; k16 < 4; k16++)
        sw[k16] = (uint32_t)(((k16*2 + lc) ^ (lr & 7)) * 16);
    const uint32_t baseQ = (uint32_t)((wid*16 + lr) * 128);
    const uint32_t baseK = (uint32_t)(lr * 128);

    const int mi = lane >> 3, li = lane & 7;
    uint32_t swv[4];
    #pragma unroll
    for (int dj = 0; dj < 4; dj++)
        swv[dj] = (uint32_t)(((dj*2 + (mi & 1)) ^ (li & 7)) * 16);
    const uint32_t baseV = (uint32_t)((((mi >> 1) ? 8 : 0) + li) * 128);

    uint32_t qf[4][4];
    #pragma unroll
    for (int k16 = 0; k16 < 4; k16++)
        ldsm_x4(qf[k16], qB + baseQ + sw[k16]);

    float m0 = -INFINITY, m1 = -INFINITY, l0 = 0.f, l1 = 0.f;
    float o[8][4] = {};
    const int rg0 = qrow0 + wid*16 + (lane >> 2);
    const int tig = lane & 3;

    for (int kt = 0; kt < nkv; kt++) {
        if (kt > 0) {
            CP_WAIT(1);
            __syncthreads();
        }
        if (kt + 2 < nkv) load_stage((kt + 2) % FL_NSTG, kt + 2);
        CP_COMMIT();

        const uint32_t st = stB + (kt % FL_NSTG) * FL_STG;
        const uint32_t kB = st + baseK, vB = st + FL_TB + baseV;

        // ---- S (log2-domain: Q pre-scaled by 0.125*log2e) ----
        float s[8][4] = {};
        #pragma unroll
        for (int k16 = 0; k16 < 4; k16++) {
            uint32_t kf[8][2];
            #pragma unroll
            for (int jj = 0; jj < 4; jj++) {
                uint32_t t0[4];
                ldsm_x4(t0, kB + jj*2048 + sw[k16]);
                kf[jj*2][0] = t0[0]; kf[jj*2][1] = t0[2];
                kf[jj*2+1][0] = t0[1]; kf[jj*2+1][1] = t0[3];
            }
            #pragma unroll
            for (int j = 0; j < 8; j++)
                mma_fp16(s[j], qf[k16], kf[j]);
        }

        if (kt >= 2*qt) {
            #pragma unroll
            for (int j = 0; j < 8; j++) {
                int c0 = kt*64 + j*8 + tig*2;
                if (c0     > rg0)     s[j][0] = -INFINITY;
                if (c0 + 1 > rg0)     s[j][1] = -INFINITY;
                if (c0     > rg0 + 8) s[j][2] = -INFINITY;
                if (c0 + 1 > rg0 + 8) s[j][3] = -INFINITY;
            }
        }

        float tm0 = -INFINITY, tm1 = -INFINITY;
        #pragma unroll
        for (int j = 0; j < 8; j++) {
            tm0 = fmaxf(tm0, fmaxf(s[j][0], s[j][1]));
            tm1 = fmaxf(tm1, fmaxf(s[j][2], s[j][3]));
        }
        tm0 = fmaxf(tm0, __shfl_xor_sync(0xffffffff, tm0, 1));
        tm0 = fmaxf(tm0, __shfl_xor_sync(0xffffffff, tm0, 2));
        tm1 = fmaxf(tm1, __shfl_xor_sync(0xffffffff, tm1, 1));
        tm1 = fmaxf(tm1, __shfl_xor_sync(0xffffffff, tm1, 2));
        float mn0 = fmaxf(m0, tm0), mn1 = fmaxf(m1, tm1);
        float a0 = exp2f(m0 - mn0), a1 = exp2f(m1 - mn1);

        uint32_t pH01[8], pH23[8];
        float rs0 = 0.f, rs1 = 0.f;
        #pragma unroll
        for (int j = 0; j < 8; j++) {
            __half2 d01 = __floats2half2_rn(fmaxf(s[j][0] - mn0, -30.f),
                                            fmaxf(s[j][1] - mn0, -30.f));
            __half2 d23 = __floats2half2_rn(fmaxf(s[j][2] - mn1, -30.f),
                                            fmaxf(s[j][3] - mn1, -30.f));
            uint32_t e01 = h2ex2(*(uint32_t*)&d01);
            uint32_t e23 = h2ex2(*(uint32_t*)&d23);
            pH01[j] = e01;
            pH23[j] = e23;
            float2 f01 = __half22float2(*(__half2*)&e01);
            float2 f23 = __half22float2(*(__half2*)&e23);
            rs0 += f01.x + f01.y;
            rs1 += f23.x + f23.y;
        }
        rs0 += __shfl_xor_sync(0xffffffff, rs0, 1);
        rs0 += __shfl_xor_sync(0xffffffff, rs0, 2);
        rs1 += __shfl_xor_sync(0xffffffff, rs1, 1);
        rs1 += __shfl_xor_sync(0xffffffff, rs1, 2);
        l0 = l0 * a0 + rs0;
        l1 = l1 * a1 + rs1;
        m0 = mn0; m1 = mn1;

        #pragma unroll
        for (int j = 0; j < 8; j++) {
            o[j][0] *= a0; o[j][1] *= a0;
            o[j][2] *= a1; o[j][3] *= a1;
        }

        #pragma unroll
        for (int c16 = 0; c16 < 4; c16++) {
            uint32_t aH[4] = { pH01[2*c16], pH23[2*c16], pH01[2*c16+1], pH23[2*c16+1] };
            #pragma unroll
            for (int dj = 0; dj < 4; dj++) {
                uint32_t t0[4];
                ldsm_x4_t(t0, vB + c16*2048 + swv[dj]);
                uint32_t v0[2] = { t0[0], t0[2] }, v1[2] = { t0[1], t0[3] };
                mma_fp16(o[dj*2],   aH, v0);
                mma_fp16(o[dj*2+1], aH, v1);
            }
        }
    }

    const float i0 = 1.f / l0, i1 = 1.f / l1;
    const size_t r0g = grow0 + wid*16 + (lane >> 2);
    #pragma unroll
    for (int j = 0; j < 8; j++) {
        const int n = colb + j*8 + tig*2;
        *(__half2*)(oh + r0g*EE + n)     = __floats2half2_rn(o[j][0]*i0, o[j][1]*i0);
        *(__half2*)(oh + (r0g+8)*EE + n) = __floats2half2_rn(o[j][2]*i1, o[j][3]*i1);
    }
}

// ---------------- launch ----------------------------------------------------
extern "C" void kernel_launch(void* const* d_in, const int* in_sizes, int n_in,
                              void* d_out, int out_size) {
    const float* x  = (const float*)d_in[0];
    const float* Wq = (const float*)d_in[1];
    const float* Wk = (const float*)d_in[2];
    const float* Wv = (const float*)d_in[3];
    const float* Wo = (const float*)d_in[4];
    const float* bo = (const float*)d_in[5];
    float* out = (float*)d_out;

    __half *p_rxh, *p_xh, *p_qh, *p_kh, *p_vh, *p_ath, *p_wh;
    cudaGetSymbolAddress((void**)&p_rxh, g_rxh);
    cudaGetSymbolAddress((void**)&p_xh,  g_xh);
    cudaGetSymbolAddress((void**)&p_qh,  g_qh);
    cudaGetSymbolAddress((void**)&p_kh,  g_kh);
    cudaGetSymbolAddress((void**)&p_vh,  g_vh);
    cudaGetSymbolAddress((void**)&p_ath, g_ath);
    cudaGetSymbolAddress((void**)&p_wh,  g_wh);

    cudaFuncSetAttribute(hmma_gemm16_kernel<0>,
                         cudaFuncAttributeMaxDynamicSharedMemorySize, GEMM16_SMEM);
    cudaFuncSetAttribute(hmma_gemm16_kernel<1>,
                         cudaFuncAttributeMaxDynamicSharedMemorySize, GEMM16_SMEM);
    cudaFuncSetAttribute(flash_hmma_kernel,
                         cudaFuncAttributeMaxDynamicSharedMemorySize, FL_SMEM);

    theta_kernel<<<2, 256>>>();
    rope_fused_kernel<<<(MM*E2 + 255)/256, 256>>>(x);
    dim3 sgrid((EE*EE + 255)/256, 4);
    split_all_kernel<<<sgrid, 256>>>(Wq, Wk, Wv, Wo);

    // persistent fused Q/K/V projection (Q output pre-scaled by QSCALE)
    hmma_gemm16_kernel<0><<<GPERS_GRID, 256, GEMM16_SMEM>>>(
        p_rxh, p_xh, p_wh, p_qh, p_kh, p_vh, nullptr, nullptr);

    dim3 fgrid(TT/128, BB*HH);         // (16, 64)
    flash_hmma_kernel<<<fgrid, 256, FL_SMEM>>>(p_qh, p_kh, p_vh, p_ath);

    // persistent O-projection; base weight pointer (z=3 offsets once).
    hmma_gemm16_kernel<1><<<GPERS_GRID, 256, GEMM16_SMEM>>>(
        p_ath, nullptr, p_wh, nullptr, nullptr, nullptr, out, bo);
}

// round 17
// speedup vs baseline: 1.0082x; 1.0082x over previous
#include <cuda_runtime.h>
#include <cuda_fp16.h>
#include <math.h>
#include <stdint.h>

// Problem constants
#define BB 4
#define TT 2048
#define EE 1024
#define HH 16
#define HD 64
#define MM (BB*TT)          // 8192 rows
#define E2 (EE/2)           // 512 pairs
#define GK 1024

// Q is pre-scaled by 0.125*log2(e) so flash softmax runs in base-2 domain.
#define QSCALE 0.18033688011112042f

// ---------------- scratch (device globals; no allocation allowed) ----------
__device__ float g_theta[E2];

__device__ __align__(256) __half g_rxh [MM*EE];   // RoPE(x), fp16
__device__ __align__(256) __half g_xh  [MM*EE];   // x, fp16
__device__ __align__(256) __half g_qh  [MM*EE];   // Q fp16 (pre-scaled)
__device__ __align__(256) __half g_kh  [MM*EE];   // K fp16
__device__ __align__(256) __half g_vh  [MM*EE];   // V fp16
__device__ __align__(256) __half g_ath [MM*EE];   // attention out fp16
__device__ __align__(256) __half g_wh  [4][EE*EE];  // Wq,Wk,Wv,Wo fp16

// ================= helpers (compute_80-level PTX only!) =====================
__device__ __forceinline__ uint32_t smem_u32(const void* p) {
    uint32_t a;
    asm("{ .reg .u64 t; cvta.to.shared.u64 t, %1; cvt.u32.u64 %0, t; }"
        : "=r"(a) : "l"(p));
    return a;
}
__device__ __forceinline__ void cp16(uint32_t saddr, const void* g) {
    asm volatile("cp.async.cg.shared.global [%0], [%1], 16;"
                 :: "r"(saddr), "l"(g) : "memory");
}
#define CP_COMMIT() asm volatile("cp.async.commit_group;" ::: "memory")
#define CP_WAIT(n)  asm volatile("cp.async.wait_group %0;" :: "n"(n) : "memory")

__device__ __forceinline__ void ldsm_x4(uint32_t* r, uint32_t addr) {
    asm volatile("ldmatrix.sync.aligned.m8n8.x4.shared.b16 {%0,%1,%2,%3}, [%4];"
                 : "=r"(r[0]), "=r"(r[1]), "=r"(r[2]), "=r"(r[3]) : "r"(addr));
}
__device__ __forceinline__ void ldsm_x4_t(uint32_t* r, uint32_t addr) {
    asm volatile("ldmatrix.sync.aligned.m8n8.x4.trans.shared.b16 {%0,%1,%2,%3}, [%4];"
                 : "=r"(r[0]), "=r"(r[1]), "=r"(r[2]), "=r"(r[3]) : "r"(addr));
}
__device__ __forceinline__ void mma_fp16(float* c, const uint32_t* a,
                                         const uint32_t* b) {
    asm volatile(
        "mma.sync.aligned.m16n8k16.row.col.f32.f16.f16.f32 "
        "{%0,%1,%2,%3}, {%4,%5,%6,%7}, {%8,%9}, {%0,%1,%2,%3};"
        : "+f"(c[0]), "+f"(c[1]), "+f"(c[2]), "+f"(c[3])
        : "r"(a[0]), "r"(a[1]), "r"(a[2]), "r"(a[3]), "r"(b[0]), "r"(b[1]));
}
// packed half2 2^x (one MUFU for two elements)
__device__ __forceinline__ uint32_t h2ex2(uint32_t x) {
    uint32_t r;
    asm("ex2.approx.f16x2 %0, %1;" : "=r"(r) : "r"(x));
    return r;
}

// ---------------- theta table ------------------------------------------------
__global__ void theta_kernel() {
    int p = blockIdx.x * blockDim.x + threadIdx.x;
    if (p >= E2) return;
    g_theta[p] = (float)exp((-(double)(2*p) / (double)EE) * log(10000.0));
}

// ---------------- fused RoPE (fp16 out) + x fp16 ------------------------------
#define P2HI 6.2831854820251465f
#define P2LO -1.7484555e-7f
#define INV2PI 0.15915494309189535f

__global__ void rope_fused_kernel(const float* __restrict__ x) {
    int idx = blockIdx.x * blockDim.x + threadIdx.x;   // over MM*E2 pairs
    if (idx >= MM*E2) return;
    int bt = idx / E2;
    int p  = idx % E2;
    int t  = bt % TT;
    float2 v = ((const float2*)x)[idx];
    float ang = (float)t * g_theta[p];      // fp32 rounding as in reference
    float n = rintf(ang * INV2PI);
    float r = fmaf(-n, P2HI, ang);
    r = fmaf(-n, P2LO, r);
    float s, c;
    __sincosf(r, &s, &c);                   // |r|<=pi: approx err ~1e-6 << fp16
    float rx = v.x * c - v.y * s;
    float ry = v.y * c + v.x * s;
    ((__half2*)g_rxh)[idx] = __floats2half2_rn(rx, ry);
    ((__half2*)g_xh)[idx]  = __floats2half2_rn(v.x, v.y);
}

// ---------------- all-W fp16 convert (one launch) -----------------------------
__global__ void split_all_kernel(const float* __restrict__ Wq,
                                 const float* __restrict__ Wk,
                                 const float* __restrict__ Wv,
                                 const float* __restrict__ Wo) {
    int i = blockIdx.x * blockDim.x + threadIdx.x;
    if (i >= EE*EE) return;
    int w = blockIdx.y;
    const float* src = (w == 0) ? Wq : (w == 1) ? Wk : (w == 2) ? Wv : Wo;
    g_wh[w][i] = __float2half_rn(src[i]);
}

// ---------------- persistent single-term fp16 NT GEMM, 3-stage, 2 CTAs/SM ----
// (R15 inner loop: let ptxas schedule fragment loads — R16 manual pipeline hurt)
#define KSTEPS (GK/64)          // 16
#define TILE_B 16384            // 128 rows x 128 bytes
#define STG16_B (2*TILE_B)      // A|W = 32 KB
#define GEMM16_SMEM (3*STG16_B) // 96 KB -> 2 CTAs/SM
#define GPERS_GRID 304          // 152 SMs x 2 CTAs

template<int OUT>
__global__ __launch_bounds__(256, 2)
void hmma_gemm16_kernel(const __half* __restrict__ A0,
                        const __half* __restrict__ A2,
                        const __half* __restrict__ W0,
                        __half* __restrict__ C16_0,
                        __half* __restrict__ C16_1,
                        __half* __restrict__ C16_2,
                        float* __restrict__ C32,
                        const float* __restrict__ bias) {
    extern __shared__ char sm[];
    const int tid  = threadIdx.x;
    const int wid  = tid >> 5;
    const int lane = tid & 31;
    const uint32_t sbase = smem_u32(sm);
    const int wm = wid >> 2;
    const int wn = wid & 3;
    const int G  = (int)gridDim.x;
    const int bx = (int)blockIdx.x;
    const int T  = (OUT == 0) ? 1536 : 512;
    const int nt = (T - bx + G - 1) / G;
    const int NC = nt << 4;

    auto tile_of = [&](int c, int& z, int& r0, int& c0) {
        int t = bx + (c >> 4) * G;
        if (OUT == 0) { z = t / 512; int rem = t & 511; r0 = (rem >> 3) << 7; c0 = (rem & 7) << 7; }
        else          { z = 3;       r0 = (t >> 3) << 7; c0 = (t & 7) << 7; }
    };

    auto load_chunk = [&](int s, int c) {
        if (c >= NC) return;
        int z, r0, c0; tile_of(c, z, r0, c0);
        const int k0 = (c & 15) * 64;
        const __half* A = (OUT == 0 && z == 2) ? A2 : A0;
        const __half* srcs[2] = { A, W0 + (size_t)z*EE*EE };
        const uint32_t st = sbase + s * STG16_B;
        #pragma unroll
        for (int t = 0; t < 2; t++) {
            const int rb = (t == 0) ? r0 : c0;
            #pragma unroll
            for (int it = 0; it < 4; it++) {
                int u = tid + 256 * it;
                int r = u >> 3, cc = u & 7;
                const __half* g = srcs[t] + (size_t)(rb + r) * GK + k0 + cc * 8;
                uint32_t sa = st + t * TILE_B + r * 128 + ((cc ^ (r & 7)) * 16);
                cp16(sa, g);
            }
        }
    };

    load_chunk(0, 0); CP_COMMIT();
    load_chunk(1, 1); CP_COMMIT();

    float acc[4][4][4] = {};
    const int lr = lane & 15, lc = lane >> 4;

    uint32_t sw[4];
    #pragma unroll
    for (int k16 = 0; k16 < 4; k16++)
        sw[k16] = (uint32_t)(((k16*2 + lc) ^ (lr & 7)) * 16);
    const uint32_t baseA = (uint32_t)((wm*64 + lr) * 128);
    const uint32_t baseW = (uint32_t)((wn*32 + lr) * 128);

    for (int c = 0; c < NC; c++) {
        CP_WAIT(1);
        __syncthreads();
        // stage (c+2)%3 was consumed in chunk c-1 (ordered by this barrier)
        load_chunk((c + 2) % 3, c + 2);
        CP_COMMIT();

        const uint32_t st = sbase + (c % 3) * STG16_B;
        const uint32_t aB = st + baseA;
        const uint32_t whB = st + TILE_B + baseW;

        #pragma unroll
        for (int k16 = 0; k16 < 4; k16++) {
            const uint32_t s16 = sw[k16];
            uint32_t a[4][4], wh[4][2];
            #pragma unroll
            for (int i = 0; i < 4; i++)
                ldsm_x4(a[i], aB + i*2048 + s16);
            #pragma unroll
            for (int jj = 0; jj < 2; jj++) {
                uint32_t t0[4];
                ldsm_x4(t0, whB + jj*2048 + s16);
                wh[jj*2][0] = t0[0]; wh[jj*2][1] = t0[2];
                wh[jj*2+1][0] = t0[1]; wh[jj*2+1][1] = t0[3];
            }
            #pragma unroll
            for (int i = 0; i < 4; i++)
                #pragma unroll
                for (int j = 0; j < 4; j++)
                    mma_fp16(acc[i][j], a[i], wh[j]);
        }

        if ((c & 15) == 15) {
            int z, r0, c0; tile_of(c, z, r0, c0);
            const int gq = lane >> 2, tig = lane & 3;
            __half* C16 = (OUT == 0)
                ? ((z == 0) ? C16_0 : (z == 1) ? C16_1 : C16_2) : nullptr;
            const float osc = (OUT == 0 && z == 0) ? QSCALE : 1.f;
            #pragma unroll
            for (int j = 0; j < 4; j++) {
                const int n = c0 + wn*32 + j*8 + tig*2;
                float b0 = 0.f, b1 = 0.f;
                if (OUT == 1) { b0 = bias[n]; b1 = bias[n+1]; }
                #pragma unroll
                for (int i = 0; i < 4; i++) {
                    const int m0 = r0 + wm*64 + i*16 + gq;
                    if (OUT == 0) {
                        *(__half2*)(C16 + (size_t)m0*GK + n) =
                            __floats2half2_rn(acc[i][j][0]*osc, acc[i][j][1]*osc);
                        *(__half2*)(C16 + (size_t)(m0+8)*GK + n) =
                            __floats2half2_rn(acc[i][j][2]*osc, acc[i][j][3]*osc);
                    } else {
                        *(float2*)(C32 + (size_t)m0 * GK + n) =
                            make_float2(acc[i][j][0] + b0, acc[i][j][1] + b1);
                        *(float2*)(C32 + (size_t)(m0 + 8) * GK + n) =
                            make_float2(acc[i][j][2] + b0, acc[i][j][3] + b1);
                    }
                }
            }
            #pragma unroll
            for (int i = 0; i < 4; i++)
                #pragma unroll
                for (int j = 0; j < 4; j++) {
                    acc[i][j][0] = 0.f; acc[i][j][1] = 0.f;
                    acc[i][j][2] = 0.f; acc[i][j][3] = 0.f;
                }
        }
    }
}

// ---------------- HMMA flash attention (causal, fp16, base-2 softmax) --------
// l is kept PER-LANE (each lane's own columns), rescaled like o each tile;
// the quad reduction happens ONCE after the loop (saves 4 shfls per tile).
#define FL_QB   16384
#define FL_TB   8192
#define FL_STG  (2*FL_TB)
#define FL_NSTG 3
#define FL_SMEM (FL_QB + FL_NSTG*FL_STG)   // 64 KB

__global__ __launch_bounds__(256, 2)
void flash_hmma_kernel(const __half* __restrict__ qh,
                       const __half* __restrict__ kh,
                       const __half* __restrict__ vh,
                       __half* __restrict__ oh) {
    extern __shared__ char sm[];
    const int tid  = threadIdx.x;
    const int wid  = tid >> 5;
    const int lane = tid & 31;
    const int qt = (int)(gridDim.x - 1 - blockIdx.x);   // heavy tiles first
    const int bh = blockIdx.y;
    const int b = bh >> 4, h = bh & 15;
    const int qrow0 = qt * 128;
    const size_t grow0 = (size_t)b * TT + qrow0;
    const int colb = h * HD;

    const uint32_t sb  = smem_u32(sm);
    const uint32_t qB  = sb;
    const uint32_t stB = sb + FL_QB;

    #pragma unroll
    for (int it = 0; it < 4; it++) {
        int u = tid + 256 * it;
        int r = u >> 3, c = u & 7;
        cp16(qB + r*128 + ((c ^ (r & 7)) * 16),
             qh + (grow0 + r) * EE + colb + c * 8);
    }
    const __half* ksrc[2] = { kh, vh };
    auto load_stage = [&](int s, int kt) {
        const size_t krow = (size_t)b * TT + kt * 64;
        const uint32_t st = stB + s * FL_STG;
        #pragma unroll
        for (int t = 0; t < 2; t++) {
            #pragma unroll
            for (int it = 0; it < 2; it++) {
                int u = tid + 256 * it;
                int r = u >> 3, c = u & 7;
                cp16(st + t*FL_TB + r*128 + ((c ^ (r & 7)) * 16),
                     ksrc[t] + (krow + r) * EE + colb + c * 8);
            }
        }
    };
    const int nkv = 2*qt + 2;
    load_stage(0, 0); CP_COMMIT();
    if (1 < nkv) load_stage(1, 1);
    CP_COMMIT();

    CP_WAIT(1);
    __syncthreads();

    const int lr = lane & 15, lc = lane >> 4;
    uint32_t sw[4];
    #pragma unroll
    for (int k16 = 0; k16 < 4; k16++)
        sw[k16] = (uint32_t)(((k16*2 + lc) ^ (lr & 7)) * 16);
    const uint32_t baseQ = (uint32_t)((wid*16 + lr) * 128);
    const uint32_t baseK = (uint32_t)(lr * 128);

    const int mi = lane >> 3, li = lane & 7;
    uint32_t swv[4];
    #pragma unroll
    for (int dj = 0; dj < 4; dj++)
        swv[dj] = (uint32_t)(((dj*2 + (mi & 1)) ^ (li & 7)) * 16);
    const uint32_t baseV = (uint32_t)((((mi >> 1) ? 8 : 0) + li) * 128);

    uint32_t qf[4][4];
    #pragma unroll
    for (int k16 = 0; k16 < 4; k16++)
        ldsm_x4(qf[k16], qB + baseQ + sw[k16]);

    float m0 = -INFINITY, m1 = -INFINITY;
    float l0 = 0.f, l1 = 0.f;              // per-lane partial row sums
    float o[8][4] = {};
    const int rg0 = qrow0 + wid*16 + (lane >> 2);
    const int tig = lane & 3;

    for (int kt = 0; kt < nkv; kt++) {
        if (kt > 0) {
            CP_WAIT(1);
            __syncthreads();
        }
        if (kt + 2 < nkv) load_stage((kt + 2) % FL_NSTG, kt + 2);
        CP_COMMIT();

        const uint32_t st = stB + (kt % FL_NSTG) * FL_STG;
        const uint32_t kB = st + baseK, vB = st + FL_TB + baseV;

        // ---- S (log2-domain: Q pre-scaled by 0.125*log2e) ----
        float s[8][4] = {};
        #pragma unroll
        for (int k16 = 0; k16 < 4; k16++) {
            uint32_t kf[8][2];
            #pragma unroll
            for (int jj = 0; jj < 4; jj++) {
                uint32_t t0[4];
                ldsm_x4(t0, kB + jj*2048 + sw[k16]);
                kf[jj*2][0] = t0[0]; kf[jj*2][1] = t0[2];
                kf[jj*2+1][0] = t0[1]; kf[jj*2+1][1] = t0[3];
            }
            #pragma unroll
            for (int j = 0; j < 8; j++)
                mma_fp16(s[j], qf[k16], kf[j]);
        }

        if (kt >= 2*qt) {
            #pragma unroll
            for (int j = 0; j < 8; j++) {
                int c0 = kt*64 + j*8 + tig*2;
                if (c0     > rg0)     s[j][0] = -INFINITY;
                if (c0 + 1 > rg0)     s[j][1] = -INFINITY;
                if (c0     > rg0 + 8) s[j][2] = -INFINITY;
                if (c0 + 1 > rg0 + 8) s[j][3] = -INFINITY;
            }
        }

        // ---- row max (quad reduce still required for stability) ----
        float tm0 = -INFINITY, tm1 = -INFINITY;
        #pragma unroll
        for (int j = 0; j < 8; j++) {
            tm0 = fmaxf(tm0, fmaxf(s[j][0], s[j][1]));
            tm1 = fmaxf(tm1, fmaxf(s[j][2], s[j][3]));
        }
        tm0 = fmaxf(tm0, __shfl_xor_sync(0xffffffff, tm0, 1));
        tm0 = fmaxf(tm0, __shfl_xor_sync(0xffffffff, tm0, 2));
        tm1 = fmaxf(tm1, __shfl_xor_sync(0xffffffff, tm1, 1));
        tm1 = fmaxf(tm1, __shfl_xor_sync(0xffffffff, tm1, 2));
        float mn0 = fmaxf(m0, tm0), mn1 = fmaxf(m1, tm1);
        float a0 = exp2f(m0 - mn0), a1 = exp2f(m1 - mn1);

        uint32_t pH01[8], pH23[8];
        float rs0 = 0.f, rs1 = 0.f;
        #pragma unroll
        for (int j = 0; j < 8; j++) {
            __half2 d01 = __floats2half2_rn(fmaxf(s[j][0] - mn0, -30.f),
                                            fmaxf(s[j][1] - mn0, -30.f));
            __half2 d23 = __floats2half2_rn(fmaxf(s[j][2] - mn1, -30.f),
                                            fmaxf(s[j][3] - mn1, -30.f));
            uint32_t e01 = h2ex2(*(uint32_t*)&d01);
            uint32_t e23 = h2ex2(*(uint32_t*)&d23);
            pH01[j] = e01;
            pH23[j] = e23;
            float2 f01 = __half22float2(*(__half2*)&e01);
            float2 f23 = __half22float2(*(__half2*)&e23);
            rs0 += f01.x + f01.y;
            rs1 += f23.x + f23.y;
        }
        // per-lane l update (quad reduction deferred to the end)
        l0 = l0 * a0 + rs0;
        l1 = l1 * a1 + rs1;
        m0 = mn0; m1 = mn1;

        #pragma unroll
        for (int j = 0; j < 8; j++) {
            o[j][0] *= a0; o[j][1] *= a0;
            o[j][2] *= a1; o[j][3] *= a1;
        }

        #pragma unroll
        for (int c16 = 0; c16 < 4; c16++) {
            uint32_t aH[4] = { pH01[2*c16], pH23[2*c16], pH01[2*c16+1], pH23[2*c16+1] };
            #pragma unroll
            for (int dj = 0; dj < 4; dj++) {
                uint32_t t0[4];
                ldsm_x4_t(t0, vB + c16*2048 + swv[dj]);
                uint32_t v0[2] = { t0[0], t0[2] }, v1[2] = { t0[1], t0[3] };
                mma_fp16(o[dj*2],   aH, v0);
                mma_fp16(o[dj*2+1], aH, v1);
            }
        }
    }

    // ---- final quad reduce of l, then normalize + store ----
    l0 += __shfl_xor_sync(0xffffffff, l0, 1);
    l0 += __shfl_xor_sync(0xffffffff, l0, 2);
    l1 += __shfl_xor_sync(0xffffffff, l1, 1);
    l1 += __shfl_xor_sync(0xffffffff, l1, 2);
    const float i0 = 1.f / l0, i1 = 1.f / l1;
    const size_t r0g = grow0 + wid*16 + (lane >> 2);
    #pragma unroll
    for (int j = 0; j < 8; j++) {
        const int n = colb + j*8 + tig*2;
        *(__half2*)(oh + r0g*EE + n)     = __floats2half2_rn(o[j][0]*i0, o[j][1]*i0);
        *(__half2*)(oh + (r0g+8)*EE + n) = __floats2half2_rn(o[j][2]*i1, o[j][3]*i1);
    }
}

// ---------------- launch ----------------------------------------------------
extern "C" void kernel_launch(void* const* d_in, const int* in_sizes, int n_in,
                              void* d_out, int out_size) {
    const float* x  = (const float*)d_in[0];
    const float* Wq = (const float*)d_in[1];
    const float* Wk = (const float*)d_in[2];
    const float* Wv = (const float*)d_in[3];
    const float* Wo = (const float*)d_in[4];
    const float* bo = (const float*)d_in[5];
    float* out = (float*)d_out;

    __half *p_rxh, *p_xh, *p_qh, *p_kh, *p_vh, *p_ath, *p_wh;
    cudaGetSymbolAddress((void**)&p_rxh, g_rxh);
    cudaGetSymbolAddress((void**)&p_xh,  g_xh);
    cudaGetSymbolAddress((void**)&p_qh,  g_qh);
    cudaGetSymbolAddress((void**)&p_kh,  g_kh);
    cudaGetSymbolAddress((void**)&p_vh,  g_vh);
    cudaGetSymbolAddress((void**)&p_ath, g_ath);
    cudaGetSymbolAddress((void**)&p_wh,  g_wh);

    cudaFuncSetAttribute(hmma_gemm16_kernel<0>,
                         cudaFuncAttributeMaxDynamicSharedMemorySize, GEMM16_SMEM);
    cudaFuncSetAttribute(hmma_gemm16_kernel<1>,
                         cudaFuncAttributeMaxDynamicSharedMemorySize, GEMM16_SMEM);
    cudaFuncSetAttribute(flash_hmma_kernel,
                         cudaFuncAttributeMaxDynamicSharedMemorySize, FL_SMEM);

    theta_kernel<<<2, 256>>>();
    rope_fused_kernel<<<(MM*E2 + 255)/256, 256>>>(x);
    dim3 sgrid((EE*EE + 255)/256, 4);
    split_all_kernel<<<sgrid, 256>>>(Wq, Wk, Wv, Wo);

    // persistent fused Q/K/V projection (Q output pre-scaled by QSCALE)
    hmma_gemm16_kernel<0><<<GPERS_GRID, 256, GEMM16_SMEM>>>(
        p_rxh, p_xh, p_wh, p_qh, p_kh, p_vh, nullptr, nullptr);

    dim3 fgrid(TT/128, BB*HH);         // (16, 64)
    flash_hmma_kernel<<<fgrid, 256, FL_SMEM>>>(p_qh, p_kh, p_vh, p_ath);

    // persistent O-projection; base weight pointer (z=3 offsets once).
    hmma_gemm16_kernel<1><<<GPERS_GRID, 256, GEMM16_SMEM>>>(
        p_ath, nullptr, p_wh, nullptr, nullptr, nullptr, out, bo);
}